// round 12
// baseline (speedup 1.0000x reference)
#include <cuda_runtime.h>
#include <cuda_fp16.h>
#include <cstdint>

// Problem constants
#define B_  2
#define S_  2048
#define D_  1024
#define H_  16
#define DK_ 64
#define M_  (B_*S_)   // 4096 rows

// fp16 scratch (device globals: allocation-free)
__device__ __half g_qh[4194304];   // inputs converted to half
__device__ __half g_kh[4194304];
__device__ __half g_vh[4194304];
__device__ __half g_wq[1048576];   // weights converted to half
__device__ __half g_wk[1048576];
__device__ __half g_wv[1048576];
__device__ __half g_wo[1048576];
__device__ __half g_q[4194304];    // projected, [B,H,S,DK], q pre-scaled by 1/8
__device__ __half g_k[4194304];
__device__ __half g_v[4194304];
__device__ __half g_attn[4194304]; // [B,S,D] half

// ---------------------------------------------------------------------------
// helpers
// ---------------------------------------------------------------------------
__device__ __forceinline__ unsigned f2h2(float lo, float hi) {
    __half2 h = __floats2half2_rn(lo, hi);
    return *(unsigned*)&h;
}

__device__ __forceinline__ uint32_t smem_u32(const void* p) {
    uint32_t a;
    asm("{ .reg .u64 t; cvta.to.shared.u64 t, %1; cvt.u32.u64 %0, t; }" : "=r"(a) : "l"(p));
    return a;
}

__device__ __forceinline__ void mma_f16(float c[4], const unsigned a[4], unsigned b0, unsigned b1) {
    asm volatile(
        "mma.sync.aligned.m16n8k16.row.col.f32.f16.f16.f32 "
        "{%0,%1,%2,%3}, {%4,%5,%6,%7}, {%8,%9}, {%0,%1,%2,%3};"
        : "+f"(c[0]), "+f"(c[1]), "+f"(c[2]), "+f"(c[3])
        : "r"(a[0]), "r"(a[1]), "r"(a[2]), "r"(a[3]),
          "r"(b0), "r"(b1));
}

__device__ __forceinline__ void ldsm_x4(unsigned r[4], uint32_t addr) {
    asm volatile("ldmatrix.sync.aligned.m8n8.x4.shared.b16 {%0,%1,%2,%3}, [%4];"
                 : "=r"(r[0]), "=r"(r[1]), "=r"(r[2]), "=r"(r[3]) : "r"(addr));
}
__device__ __forceinline__ void ldsm_x4_t(unsigned r[4], uint32_t addr) {
    asm volatile("ldmatrix.sync.aligned.m8n8.x4.trans.shared.b16 {%0,%1,%2,%3}, [%4];"
                 : "=r"(r[0]), "=r"(r[1]), "=r"(r[2]), "=r"(r[3]) : "r"(addr));
}

// Fast e^x on the FMA/ALU pipes (no MUFU). Handles very negative x (mask) -> ~0.
__device__ __forceinline__ float fexp(float x) {
    float y = x * 1.44269504089f;          // log2(e)
    y = fmaxf(y, -126.0f);
    float z = __fadd_rn(y, 12582912.0f);   // rint via magic number
    int   iz = __float_as_int(z);
    float k = __fadd_rn(z, -12582912.0f);
    float f = y - k;                       // f in [-0.5, 0.5]
    float u = f * 0.69314718056f;
    float p = fmaf(u, fmaf(u, fmaf(u, fmaf(u, 0.041666668f, 0.16666667f), 0.5f), 1.0f), 1.0f);
    return __int_as_float(__float_as_int(p) + (iz << 23));  // p * 2^k
}

// ---------------------------------------------------------------------------
// Fused fp32 -> fp16 convert for all 7 tensors. blockIdx.z selects tensor.
// 4-batched grid-stride body -> MLP=8 loads in flight per thread.
// ---------------------------------------------------------------------------
__global__ __launch_bounds__(256)
void cvt_all(const float* __restrict__ Q, const float* __restrict__ K,
             const float* __restrict__ V, const float* __restrict__ Wq,
             const float* __restrict__ Wk, const float* __restrict__ Wv,
             const float* __restrict__ Wo)
{
    int z = blockIdx.z;
    const float* s;
    __half* d;
    int n8;
    switch (z) {
        case 0: s = Q;  d = g_qh; n8 = 524288; break;
        case 1: s = K;  d = g_kh; n8 = 524288; break;
        case 2: s = V;  d = g_vh; n8 = 524288; break;
        case 3: s = Wq; d = g_wq; n8 = 131072; break;
        case 4: s = Wk; d = g_wk; n8 = 131072; break;
        case 5: s = Wv; d = g_wv; n8 = 131072; break;
        default: s = Wo; d = g_wo; n8 = 131072; break;
    }
    int tid = blockIdx.x * 256 + threadIdx.x;     // 0..65535
    for (int base = tid; base < n8; base += 65536 * 4) {
        float4 a[4], b[4];
        #pragma unroll
        for (int j = 0; j < 4; ++j) {
            int i = base + j * 65536;
            if (i < n8) {
                a[j] = ((const float4*)s)[2 * i];
                b[j] = ((const float4*)s)[2 * i + 1];
            }
        }
        #pragma unroll
        for (int j = 0; j < 4; ++j) {
            int i = base + j * 65536;
            if (i < n8) {
                uint4 u;
                u.x = f2h2(a[j].x, a[j].y); u.y = f2h2(a[j].z, a[j].w);
                u.z = f2h2(b[j].x, b[j].y); u.w = f2h2(b[j].z, b[j].w);
                ((uint4*)d)[i] = u;
            }
        }
    }
}

// ---------------------------------------------------------------------------
// fp16 GEMM body (R10 structure, half operands): C = A[4096,1024]h @ W[1024,1024]h
// BM=BN=128, BK=32, 256 threads / 8 warps (4x2), warp tile 32x64, m16n8k16.
// A smem: [2][128 rows][AST=20 u32]; B smem: [2][32 k-rows][BST=68 u32].
// 2-stage: register prefetch (uint4) + store. ldmatrix.x4 / .x4.trans frags.
// MODE 0: fp32 row-major write. MODE 1: half [B,H,S,DK] head-layout write (*scale).
// ---------------------------------------------------------------------------
#define AST 20
#define BST 68

template<int MODE>
__device__ __forceinline__ void gemm_body(const __half* __restrict__ A,
                                          const __half* __restrict__ W,
                                          const float* __restrict__ bias,
                                          void* __restrict__ Cv, float scale)
{
    __shared__ unsigned As[2][128 * AST];
    __shared__ unsigned Bs[2][32 * BST];

    const int t    = threadIdx.x;
    const int lane = t & 31;
    const int warp = t >> 5;
    const int g    = lane >> 2;
    const int q    = lane & 3;

    const int bm = blockIdx.y * 128;
    const int bn = blockIdx.x * 128;
    const int wm = (warp & 3) * 32;
    const int wn = (warp >> 2) * 64;

    float acc[2][8][4];
    #pragma unroll
    for (int mt = 0; mt < 2; mt++)
        #pragma unroll
        for (int nt = 0; nt < 8; nt++)
            #pragma unroll
            for (int i = 0; i < 4; i++) acc[mt][nt][i] = 0.f;

    const uint32_t Ab = smem_u32(As);
    const uint32_t Bb = smem_u32(Bs);

    const uint32_t a_lrow = (uint32_t)(lane & 15);
    const uint32_t a_lcol = (lane & 16) ? 16u : 0u;
    const uint32_t b_lrow = (uint32_t)((lane & 7) + ((lane & 8) ? 8 : 0));
    const uint32_t b_lcol = (lane & 16) ? 16u : 0u;

    // fill mappings (uint4 = 8 halves)
    // A: 128 rows x 4 chunks = 512;  B: 32 rows x 16 chunks = 512
    const int a_row = t >> 1, a_c = (t & 1) * 2;     // 2 consecutive chunks per thread
    const int b_row = t >> 3, b_c = (t & 7) * 2;

    uint4 a_st[2], b_st[2];

    auto fill_direct = [&](int k0, int buf) {
        #pragma unroll
        for (int j = 0; j < 2; ++j) {
            uint4 v = *(const uint4*)(A + (size_t)(bm + a_row) * 1024 + k0 + (a_c + j) * 8);
            *(uint4*)&As[buf][a_row * AST + (a_c + j) * 4] = v;
        }
        #pragma unroll
        for (int j = 0; j < 2; ++j) {
            uint4 v = *(const uint4*)(W + (size_t)(k0 + b_row) * 1024 + bn + (b_c + j) * 8);
            *(uint4*)&Bs[buf][b_row * BST + (b_c + j) * 4] = v;
        }
    };

    fill_direct(0, 0);
    __syncthreads();

    for (int k0 = 0; k0 < 1024; k0 += 32) {
        int buf = (k0 >> 5) & 1;
        bool has_next = (k0 + 32) < 1024;
        if (has_next) {
            #pragma unroll
            for (int j = 0; j < 2; ++j)
                a_st[j] = *(const uint4*)(A + (size_t)(bm + a_row) * 1024 + (k0 + 32) + (a_c + j) * 8);
            #pragma unroll
            for (int j = 0; j < 2; ++j)
                b_st[j] = *(const uint4*)(W + (size_t)(k0 + 32 + b_row) * 1024 + bn + (b_c + j) * 8);
        }

        #pragma unroll
        for (int s = 0; s < 2; ++s) {
            unsigned afr[2][4];
            #pragma unroll
            for (int mt = 0; mt < 2; ++mt)
                ldsm_x4(afr[mt], Ab + (uint32_t)buf * (128 * AST * 4)
                                   + (uint32_t)(wm + mt * 16 + a_lrow) * (AST * 4)
                                   + (uint32_t)s * 32 + a_lcol);
            unsigned bfr[4][4];
            #pragma unroll
            for (int np = 0; np < 4; ++np)
                ldsm_x4_t(bfr[np], Bb + (uint32_t)buf * (32 * BST * 4)
                                     + ((uint32_t)s * 16 + b_lrow) * (BST * 4)
                                     + (uint32_t)(wn + np * 16) * 2 + b_lcol);
            #pragma unroll
            for (int mt = 0; mt < 2; ++mt)
                #pragma unroll
                for (int np = 0; np < 4; ++np) {
                    mma_f16(acc[mt][2 * np    ], afr[mt], bfr[np][0], bfr[np][1]);
                    mma_f16(acc[mt][2 * np + 1], afr[mt], bfr[np][2], bfr[np][3]);
                }
        }

        if (has_next) {
            __syncthreads();
            int nb = buf ^ 1;
            #pragma unroll
            for (int j = 0; j < 2; ++j)
                *(uint4*)&As[nb][a_row * AST + (a_c + j) * 4] = a_st[j];
            #pragma unroll
            for (int j = 0; j < 2; ++j)
                *(uint4*)&Bs[nb][b_row * BST + (b_c + j) * 4] = b_st[j];
            __syncthreads();
        }
    }

    // Epilogue
    #pragma unroll
    for (int mt = 0; mt < 2; mt++) {
        int r0 = bm + wm + mt * 16 + g;
        #pragma unroll
        for (int nt = 0; nt < 8; nt++) {
            int col = bn + wn + nt * 8 + q * 2;
            float bv0 = bias[col], bv1 = bias[col + 1];
            float v00 = (acc[mt][nt][0] + bv0) * scale;
            float v01 = (acc[mt][nt][1] + bv1) * scale;
            float v10 = (acc[mt][nt][2] + bv0) * scale;
            float v11 = (acc[mt][nt][3] + bv1) * scale;
            if (MODE == 0) {
                float* C = (float*)Cv;
                float* p0 = C + (size_t)r0 * 1024 + col;
                float* p1 = C + (size_t)(r0 + 8) * 1024 + col;
                p0[0] = v00; p0[1] = v01;
                p1[0] = v10; p1[1] = v11;
            } else {
                __half* C = (__half*)Cv;
                int h  = col >> 6;
                int dk = col & 63;
                int b0r = r0 >> 11, s0r = r0 & 2047;
                int b1r = (r0 + 8) >> 11, s1r = (r0 + 8) & 2047;
                *(unsigned*)(C + (((size_t)(b0r * H_ + h) * S_ + s0r) * DK_ + dk)) = f2h2(v00, v01);
                *(unsigned*)(C + (((size_t)(b1r * H_ + h) * S_ + s1r) * DK_ + dk)) = f2h2(v10, v11);
            }
        }
    }
}

// Fused Q/K/V projection: blockIdx.z selects projection; q pre-scaled by 1/8.
__global__ __launch_bounds__(256, 2)
void qkv_gemm(const float* __restrict__ bq, const float* __restrict__ bk,
              const float* __restrict__ bv)
{
    int z = blockIdx.z;
    const __half* A = (z == 0) ? g_qh : (z == 1) ? g_kh : g_vh;
    const __half* W = (z == 0) ? g_wq : (z == 1) ? g_wk : g_wv;
    const float*  b = (z == 0) ? bq : (z == 1) ? bk : bv;
    __half*       C = (z == 0) ? g_q : (z == 1) ? g_k : g_v;
    float scale = (z == 0) ? 0.125f : 1.0f;
    gemm_body<1>(A, W, b, C, scale);
}

__global__ __launch_bounds__(256, 2)
void out_gemm(const float* __restrict__ b, float* __restrict__ C)
{
    gemm_body<0>(g_attn, g_wo, b, C, 1.0f);
}

// ---------------------------------------------------------------------------
// fp16 causal flash attention (R10 structure, half gmem operands).
// 256 threads / 8 warps, Q tile 128 (m16/warp), K/V tile 64 keys.
// smem stride 36 u32 (144B rows) -> conflict-free ldmatrix phases.
// K frags: ldmatrix.x4; V frags: ldmatrix.x4.trans. P stays in registers.
// ---------------------------------------------------------------------------
#define FST 36
#define FLASH_U32 (64*FST + 64*FST + 8*16*FST)

__global__ __launch_bounds__(256, 2)
void flash_f16(__half* __restrict__ outh)
{
    __shared__ unsigned sm[FLASH_U32];
    unsigned* Ksh = sm;
    unsigned* Vsh = sm + 64 * FST;
    int t = threadIdx.x;
    int wid = t >> 5, lane = t & 31;
    int g = lane >> 2, q = lane & 3;
    unsigned* Qw = sm + 128 * FST + wid * 16 * FST;

    int bh = blockIdx.y;
    int b  = bh >> 4;
    int h  = bh & 15;
    int m0 = blockIdx.x * 128;
    int r0w = m0 + wid * 16;

    const __half* qbase = g_q + (size_t)bh * S_ * DK_;
    const __half* kbase = g_k + (size_t)bh * S_ * DK_;
    const __half* vbase = g_v + (size_t)bh * S_ * DK_;

    // ---- stage this warp's Q tile (16x64 half, already scaled) ----
    #pragma unroll
    for (int i = 0; i < 4; ++i) {
        int idx = lane + 32 * i;               // 0..127 uint4 chunks
        int row = idx >> 3, c = idx & 7;
        uint4 v = *(const uint4*)(qbase + (size_t)(r0w + row) * DK_ + c * 8);
        *(uint4*)&Qw[row * FST + c * 4] = v;
    }
    __syncwarp();

    const uint32_t Kb = smem_u32(Ksh);
    const uint32_t Vb = smem_u32(Vsh);
    const uint32_t Qb = smem_u32(Qw);

    unsigned aq[4][4];
    {
        uint32_t qaddr = Qb + (uint32_t)(lane & 15) * (FST * 4) + ((lane & 16) ? 16u : 0u);
        #pragma unroll
        for (int kk = 0; kk < 4; ++kk)
            ldsm_x4(aq[kk], qaddr + kk * 32);
    }

    const uint32_t k_lrow = (uint32_t)((lane & 7) + ((lane & 16) ? 8 : 0)) * (FST * 4)
                          + ((lane & 8) ? 16u : 0u);
    const uint32_t v_lrow = (uint32_t)((lane & 7) + ((lane & 8) ? 8 : 0)) * (FST * 4)
                          + ((lane & 16) ? 16u : 0u);

    float od[8][4];
    #pragma unroll
    for (int nt = 0; nt < 8; nt++)
        #pragma unroll
        for (int i = 0; i < 4; i++) od[nt][i] = 0.f;
    float mrow0 = -1e30f, mrow1 = -1e30f, lrow0 = 0.f, lrow1 = 0.f;

    int nkb = 2 * (blockIdx.x + 1);            // causal: key blocks 0..nkb-1

    for (int kb = 0; kb < nkb; ++kb) {
        int jb = kb * 64;
        __syncthreads();
        // ---- cooperative K/V tile fill (64x64 half each): pure uint4 copies ----
        #pragma unroll
        for (int i = 0; i < 4; ++i) {
            int idx = t + 256 * i;             // 0..1023
            int mat = idx >> 9;                // 0=K, 1=V
            int row = (idx >> 3) & 63;
            int c   = idx & 7;
            const __half* src = (mat ? vbase : kbase) + (size_t)(jb + row) * DK_ + c * 8;
            unsigned* dst = (mat ? Vsh : Ksh) + row * FST + c * 4;
            *(uint4*)dst = *(const uint4*)src;
        }
        __syncthreads();

        if (jb > r0w + 15) continue;

        int nplim = ((r0w + 15 - jb) >> 4) + 1;
        if (nplim > 4) nplim = 4;
        int ntlim = 2 * nplim;

        // ---- S = Q @ K^T ----
        float s[8][4];
        #pragma unroll
        for (int nt = 0; nt < 8; nt++)
            #pragma unroll
            for (int i = 0; i < 4; i++) s[nt][i] = 0.f;

        #pragma unroll
        for (int kk = 0; kk < 4; ++kk) {
            #pragma unroll
            for (int np = 0; np < 4; ++np) {
                if (np < nplim) {
                    unsigned bfr[4];
                    ldsm_x4(bfr, Kb + (uint32_t)np * (16 * FST * 4) + (uint32_t)kk * 32 + k_lrow);
                    mma_f16(s[2 * np    ], aq[kk], bfr[0], bfr[1]);
                    mma_f16(s[2 * np + 1], aq[kk], bfr[2], bfr[3]);
                }
            }
        }

        // ---- causal mask (diagonal region) ----
        if (jb + 63 > r0w) {
            int row0 = r0w + g, row1 = r0w + g + 8;
            #pragma unroll
            for (int nt = 0; nt < 8; ++nt) {
                if (nt < ntlim) {
                    int j0 = jb + nt * 8 + 2 * q;
                    if (j0     > row0) s[nt][0] = -1e30f;
                    if (j0 + 1 > row0) s[nt][1] = -1e30f;
                    if (j0     > row1) s[nt][2] = -1e30f;
                    if (j0 + 1 > row1) s[nt][3] = -1e30f;
                }
            }
        }

        // ---- online softmax ----
        float mx0 = -1e30f, mx1 = -1e30f;
        #pragma unroll
        for (int nt = 0; nt < 8; ++nt) {
            if (nt < ntlim) {
                mx0 = fmaxf(mx0, fmaxf(s[nt][0], s[nt][1]));
                mx1 = fmaxf(mx1, fmaxf(s[nt][2], s[nt][3]));
            }
        }
        mx0 = fmaxf(mx0, __shfl_xor_sync(0xffffffffu, mx0, 1));
        mx0 = fmaxf(mx0, __shfl_xor_sync(0xffffffffu, mx0, 2));
        mx1 = fmaxf(mx1, __shfl_xor_sync(0xffffffffu, mx1, 1));
        mx1 = fmaxf(mx1, __shfl_xor_sync(0xffffffffu, mx1, 2));

        float mn0 = fmaxf(mrow0, mx0);
        float mn1 = fmaxf(mrow1, mx1);
        float alpha0 = fexp(mrow0 - mn0);
        float alpha1 = fexp(mrow1 - mn1);
        mrow0 = mn0; mrow1 = mn1;

        unsigned ph0[8], ph1[8];
        float rs0 = 0.f, rs1 = 0.f;
        #pragma unroll
        for (int nt = 0; nt < 8; ++nt) {
            if (nt < ntlim) {
                float p0 = fexp(s[nt][0] - mn0);
                float p1 = fexp(s[nt][1] - mn0);
                float p2 = fexp(s[nt][2] - mn1);
                float p3 = fexp(s[nt][3] - mn1);
                rs0 += p0 + p1;
                rs1 += p2 + p3;
                ph0[nt] = f2h2(p0, p1);
                ph1[nt] = f2h2(p2, p3);
            }
        }
        rs0 += __shfl_xor_sync(0xffffffffu, rs0, 1);
        rs0 += __shfl_xor_sync(0xffffffffu, rs0, 2);
        rs1 += __shfl_xor_sync(0xffffffffu, rs1, 1);
        rs1 += __shfl_xor_sync(0xffffffffu, rs1, 2);
        lrow0 = lrow0 * alpha0 + rs0;
        lrow1 = lrow1 * alpha1 + rs1;

        #pragma unroll
        for (int nt = 0; nt < 8; ++nt) {
            od[nt][0] *= alpha0; od[nt][1] *= alpha0;
            od[nt][2] *= alpha1; od[nt][3] *= alpha1;
        }

        // ---- O += P @ V ----
        #pragma unroll
        for (int kk = 0; kk < 4; ++kk) {
            if (kk < nplim) {
                unsigned ap[4];
                ap[0] = ph0[2 * kk];
                ap[1] = ph1[2 * kk];
                ap[2] = ph0[2 * kk + 1];
                ap[3] = ph1[2 * kk + 1];
                #pragma unroll
                for (int np = 0; np < 4; ++np) {
                    unsigned bfr[4];
                    ldsm_x4_t(bfr, Vb + (uint32_t)kk * (16 * FST * 4) + (uint32_t)np * 32 + v_lrow);
                    mma_f16(od[2 * np    ], ap, bfr[0], bfr[1]);
                    mma_f16(od[2 * np + 1], ap, bfr[2], bfr[3]);
                }
            }
        }
    }

    // ---- epilogue: normalize + write half [B,S,D] ----
    float inv0 = 1.f / lrow0;
    float inv1 = 1.f / lrow1;
    int row0 = m0 + wid * 16 + g;
    int row1 = row0 + 8;
    __half* o0 = outh + ((size_t)b * S_ + row0) * D_ + h * DK_;
    __half* o1 = outh + ((size_t)b * S_ + row1) * D_ + h * DK_;
    #pragma unroll
    for (int nt = 0; nt < 8; ++nt) {
        int col = nt * 8 + 2 * q;
        *(unsigned*)(o0 + col) = f2h2(od[nt][0] * inv0, od[nt][1] * inv0);
        *(unsigned*)(o1 + col) = f2h2(od[nt][2] * inv1, od[nt][3] * inv1);
    }
}

// ---------------------------------------------------------------------------
// Launch: fused convert -> fused QKV projection -> flash -> output GEMM
// ---------------------------------------------------------------------------
extern "C" void kernel_launch(void* const* d_in, const int* in_sizes, int n_in,
                              void* d_out, int out_size)
{
    const float* Q   = (const float*)d_in[0];
    const float* K   = (const float*)d_in[1];
    const float* V   = (const float*)d_in[2];
    const float* W_q = (const float*)d_in[3];
    const float* b_q = (const float*)d_in[4];
    const float* W_k = (const float*)d_in[5];
    const float* b_k = (const float*)d_in[6];
    const float* W_v = (const float*)d_in[7];
    const float* b_v = (const float*)d_in[8];
    const float* W_o = (const float*)d_in[9];
    const float* b_o = (const float*)d_in[10];
    float* out = (float*)d_out;

    __half* ga;
    cudaGetSymbolAddress((void**)&ga, g_attn);

    cvt_all<<<dim3(256, 1, 7), 256>>>(Q, K, V, W_q, W_k, W_v, W_o);

    qkv_gemm<<<dim3(8, 32, 3), 256>>>(b_q, b_k, b_v);

    flash_f16<<<dim3(S_ / 128, B_ * H_), 256>>>(ga);

    out_gemm<<<dim3(8, 32), 256>>>(b_o, out);
}

// round 15
// speedup vs baseline: 1.7198x; 1.7198x over previous
#include <cuda_runtime.h>
#include <cuda_fp16.h>
#include <cstdint>

// Problem constants
#define B_  2
#define S_  2048
#define D_  1024
#define H_  16
#define DK_ 64
#define M_  (B_*S_)   // 4096 rows

// fp16 scratch (device globals: allocation-free)
__device__ __half g_qh[4194304];   // inputs converted to half
__device__ __half g_kh[4194304];
__device__ __half g_vh[4194304];
__device__ __half g_wq[1048576];   // weights converted to half
__device__ __half g_wk[1048576];
__device__ __half g_wv[1048576];
__device__ __half g_wo[1048576];
__device__ __half g_q[4194304];    // projected, [B,H,S,DK], q pre-scaled by 1/8
__device__ __half g_k[4194304];
__device__ __half g_v[4194304];
__device__ __half g_attn[4194304]; // [B,S,D] half

// ---------------------------------------------------------------------------
// helpers
// ---------------------------------------------------------------------------
__device__ __forceinline__ unsigned f2h2(float lo, float hi) {
    __half2 h = __floats2half2_rn(lo, hi);
    return *(unsigned*)&h;
}

__device__ __forceinline__ uint32_t smem_u32(const void* p) {
    uint32_t a;
    asm("{ .reg .u64 t; cvta.to.shared.u64 t, %1; cvt.u32.u64 %0, t; }" : "=r"(a) : "l"(p));
    return a;
}

__device__ __forceinline__ void mma_f16(float c[4], const unsigned a[4], unsigned b0, unsigned b1) {
    asm volatile(
        "mma.sync.aligned.m16n8k16.row.col.f32.f16.f16.f32 "
        "{%0,%1,%2,%3}, {%4,%5,%6,%7}, {%8,%9}, {%0,%1,%2,%3};"
        : "+f"(c[0]), "+f"(c[1]), "+f"(c[2]), "+f"(c[3])
        : "r"(a[0]), "r"(a[1]), "r"(a[2]), "r"(a[3]),
          "r"(b0), "r"(b1));
}

__device__ __forceinline__ void ldsm_x4(unsigned r[4], uint32_t addr) {
    asm volatile("ldmatrix.sync.aligned.m8n8.x4.shared.b16 {%0,%1,%2,%3}, [%4];"
                 : "=r"(r[0]), "=r"(r[1]), "=r"(r[2]), "=r"(r[3]) : "r"(addr));
}
__device__ __forceinline__ void ldsm_x4_t(unsigned r[4], uint32_t addr) {
    asm volatile("ldmatrix.sync.aligned.m8n8.x4.trans.shared.b16 {%0,%1,%2,%3}, [%4];"
                 : "=r"(r[0]), "=r"(r[1]), "=r"(r[2]), "=r"(r[3]) : "r"(addr));
}

#define CP16(dst, src) \
    asm volatile("cp.async.cg.shared.global [%0], [%1], 16;" :: "r"(dst), "l"(src))
#define CP_COMMIT() asm volatile("cp.async.commit_group;" ::: "memory")
#define CP_WAIT(n)  asm volatile("cp.async.wait_group %0;" :: "n"(n) : "memory")

// Fast e^x on the FMA/ALU pipes (no MUFU). Handles very negative x (mask) -> ~0.
__device__ __forceinline__ float fexp(float x) {
    float y = x * 1.44269504089f;          // log2(e)
    y = fmaxf(y, -126.0f);
    float z = __fadd_rn(y, 12582912.0f);   // rint via magic number
    int   iz = __float_as_int(z);
    float k = __fadd_rn(z, -12582912.0f);
    float f = y - k;                       // f in [-0.5, 0.5]
    float u = f * 0.69314718056f;
    float p = fmaf(u, fmaf(u, fmaf(u, fmaf(u, 0.041666668f, 0.16666667f), 0.5f), 1.0f), 1.0f);
    return __int_as_float(__float_as_int(p) + (iz << 23));  // p * 2^k
}

// ---------------------------------------------------------------------------
// Fused fp32 -> fp16 convert for all 7 tensors. blockIdx.z selects tensor.
// grid.x=512 -> 131072 threads per tensor; 4-batched loads (MLP=8).
// ---------------------------------------------------------------------------
__global__ __launch_bounds__(256)
void cvt_all(const float* __restrict__ Q, const float* __restrict__ K,
             const float* __restrict__ V, const float* __restrict__ Wq,
             const float* __restrict__ Wk, const float* __restrict__ Wv,
             const float* __restrict__ Wo)
{
    int z = blockIdx.z;
    const float* s;
    __half* d;
    int n8;
    switch (z) {
        case 0: s = Q;  d = g_qh; n8 = 524288; break;
        case 1: s = K;  d = g_kh; n8 = 524288; break;
        case 2: s = V;  d = g_vh; n8 = 524288; break;
        case 3: s = Wq; d = g_wq; n8 = 131072; break;
        case 4: s = Wk; d = g_wk; n8 = 131072; break;
        case 5: s = Wv; d = g_wv; n8 = 131072; break;
        default: s = Wo; d = g_wo; n8 = 131072; break;
    }
    int tid = blockIdx.x * 256 + threadIdx.x;     // 0..131071
    float4 a[4], b[4];
    #pragma unroll
    for (int j = 0; j < 4; ++j) {
        int i = tid + j * 131072;
        if (i < n8) {
            a[j] = ((const float4*)s)[2 * i];
            b[j] = ((const float4*)s)[2 * i + 1];
        }
    }
    #pragma unroll
    for (int j = 0; j < 4; ++j) {
        int i = tid + j * 131072;
        if (i < n8) {
            uint4 u;
            u.x = f2h2(a[j].x, a[j].y); u.y = f2h2(a[j].z, a[j].w);
            u.z = f2h2(b[j].x, b[j].y); u.w = f2h2(b[j].z, b[j].w);
            ((uint4*)d)[i] = u;
        }
    }
}

// ---------------------------------------------------------------------------
// fp16 GEMM, BK=64, cp.async 3-stage ring, one __syncthreads per iteration.
// C[4096,1024] = A[4096,1024]h @ W[1024,1024]h  (+bias, *scale)
// BM=BN=128, 256 threads / 8 warps (4x2), warp tile 32x64, m16n8k16.
// A stage: 128 rows x 144B (128B data + 16 pad)  -> coalesced fill (8 thr/row),
//          conflict-free ldmatrix.x4 phases (proven stride from flash).
// B stage: 64 k-rows x 272B (256B data + 16 pad) -> coalesced fill (16 chunks/row),
//          conflict-free ldmatrix.x4.trans (proven stride from R10).
// MODE 0: fp32 row-major write. MODE 1: half [B,H,S,DK] head-layout write.
// ---------------------------------------------------------------------------
#define GS_B   18432                 // A stage bytes (128*144)
#define G_STG  35840                 // + B stage (64*272)
#define G_SMEM (3 * G_STG)           // 107520

template<int MODE>
__device__ __forceinline__ void gemm_body(const __half* __restrict__ A,
                                          const __half* __restrict__ W,
                                          const float* __restrict__ bias,
                                          void* __restrict__ Cv, float scale)
{
    extern __shared__ char smc[];
    const uint32_t sb = smem_u32(smc);

    const int t    = threadIdx.x;
    const int lane = t & 31;
    const int warp = t >> 5;
    const int g    = lane >> 2;
    const int q    = lane & 3;

    const int bm = blockIdx.y * 128;
    const int bn = blockIdx.x * 128;
    const int wm = (warp & 3) * 32;
    const int wn = (warp >> 2) * 64;

    float acc[2][8][4];
    #pragma unroll
    for (int mt = 0; mt < 2; mt++)
        #pragma unroll
        for (int nt = 0; nt < 8; nt++)
            #pragma unroll
            for (int i = 0; i < 4; i++) acc[mt][nt][i] = 0.f;

    const uint32_t a_lrow = (uint32_t)(lane & 15);
    const uint32_t a_lcol = (lane & 16) ? 16u : 0u;
    const uint32_t b_lrow = (uint32_t)((lane & 7) + ((lane & 8) ? 8 : 0));
    const uint32_t b_lcol = (lane & 16) ? 16u : 0u;

    // fill one k64 chunk (ck) into stage ck%3 via cp.async (all coalesced)
    auto fill = [&](int ck) {
        uint32_t base = sb + (uint32_t)(ck % 3) * G_STG;
        #pragma unroll
        for (int i = 0; i < 4; ++i) {              // A: 1024 chunks, 8/row
            int idx = t + 256 * i;
            int row = idx >> 3, c = idx & 7;
            CP16(base + (uint32_t)(row * 144 + c * 16),
                 A + (size_t)(bm + row) * 1024 + ck * 64 + c * 8);
        }
        #pragma unroll
        for (int i = 0; i < 4; ++i) {              // B: 1024 chunks, 16/row
            int idx = t + 256 * i;
            int row = idx >> 4, c = idx & 15;
            CP16(base + GS_B + (uint32_t)(row * 272 + c * 16),
                 W + (size_t)(ck * 64 + row) * 1024 + bn + c * 8);
        }
    };

    fill(0); CP_COMMIT();
    fill(1); CP_COMMIT();

    for (int it = 0; it < 16; ++it) {
        if (it < 15) { CP_WAIT(1); } else { CP_WAIT(0); }
        __syncthreads();                            // all warps done with stage (it-1)%3
        if (it + 2 < 16) { fill(it + 2); CP_COMMIT(); }

        uint32_t Abase = sb + (uint32_t)(it % 3) * G_STG;
        uint32_t Bbase = Abase + GS_B;
        #pragma unroll
        for (int s = 0; s < 4; ++s) {               // 4 x k16 steps
            unsigned afr[2][4];
            #pragma unroll
            for (int mt = 0; mt < 2; ++mt)
                ldsm_x4(afr[mt], Abase + (uint32_t)(wm + mt * 16 + a_lrow) * 144
                                       + (uint32_t)s * 32 + a_lcol);
            unsigned bfr[4][4];
            #pragma unroll
            for (int np = 0; np < 4; ++np)
                ldsm_x4_t(bfr[np], Bbase + ((uint32_t)s * 16 + b_lrow) * 272
                                         + (uint32_t)(wn + np * 16) * 2 + b_lcol);
            #pragma unroll
            for (int mt = 0; mt < 2; ++mt)
                #pragma unroll
                for (int np = 0; np < 4; ++np) {
                    mma_f16(acc[mt][2 * np    ], afr[mt], bfr[np][0], bfr[np][1]);
                    mma_f16(acc[mt][2 * np + 1], afr[mt], bfr[np][2], bfr[np][3]);
                }
        }
    }

    // Epilogue
    #pragma unroll
    for (int mt = 0; mt < 2; mt++) {
        int r0 = bm + wm + mt * 16 + g;
        #pragma unroll
        for (int nt = 0; nt < 8; nt++) {
            int col = bn + wn + nt * 8 + q * 2;
            float bv0 = bias[col], bv1 = bias[col + 1];
            float v00 = (acc[mt][nt][0] + bv0) * scale;
            float v01 = (acc[mt][nt][1] + bv1) * scale;
            float v10 = (acc[mt][nt][2] + bv0) * scale;
            float v11 = (acc[mt][nt][3] + bv1) * scale;
            if (MODE == 0) {
                float* C = (float*)Cv;
                float* p0 = C + (size_t)r0 * 1024 + col;
                float* p1 = C + (size_t)(r0 + 8) * 1024 + col;
                p0[0] = v00; p0[1] = v01;
                p1[0] = v10; p1[1] = v11;
            } else {
                __half* C = (__half*)Cv;
                int h  = col >> 6;
                int dk = col & 63;
                int b0r = r0 >> 11, s0r = r0 & 2047;
                int b1r = (r0 + 8) >> 11, s1r = (r0 + 8) & 2047;
                *(unsigned*)(C + (((size_t)(b0r * H_ + h) * S_ + s0r) * DK_ + dk)) = f2h2(v00, v01);
                *(unsigned*)(C + (((size_t)(b1r * H_ + h) * S_ + s1r) * DK_ + dk)) = f2h2(v10, v11);
            }
        }
    }
}

// Fused Q/K/V projection: blockIdx.z selects projection; q pre-scaled by 1/8.
__global__ __launch_bounds__(256, 2)
void qkv_gemm(const float* __restrict__ bq, const float* __restrict__ bk,
              const float* __restrict__ bv)
{
    int z = blockIdx.z;
    const __half* A = (z == 0) ? g_qh : (z == 1) ? g_kh : g_vh;
    const __half* W = (z == 0) ? g_wq : (z == 1) ? g_wk : g_wv;
    const float*  b = (z == 0) ? bq : (z == 1) ? bk : bv;
    __half*       C = (z == 0) ? g_q : (z == 1) ? g_k : g_v;
    float scale = (z == 0) ? 0.125f : 1.0f;
    gemm_body<1>(A, W, b, C, scale);
}

__global__ __launch_bounds__(256, 2)
void out_gemm(const float* __restrict__ b, float* __restrict__ C)
{
    gemm_body<0>(g_attn, g_wo, b, C, 1.0f);
}

// ---------------------------------------------------------------------------
// fp16 causal flash attention (R10 structure, half gmem operands),
// with REVERSED blockIdx.x: heavy (large-kv) tiles launch first (LPT).
// 256 threads / 8 warps, Q tile 128 (m16/warp), K/V tile 64 keys.
// smem stride 36 u32 (144B rows) -> conflict-free ldmatrix phases.
// ---------------------------------------------------------------------------
#define FST 36
#define FLASH_U32 (64*FST + 64*FST + 8*16*FST)

__global__ __launch_bounds__(256, 2)
void flash_f16(__half* __restrict__ outh)
{
    __shared__ unsigned sm[FLASH_U32];
    unsigned* Ksh = sm;
    unsigned* Vsh = sm + 64 * FST;
    int t = threadIdx.x;
    int wid = t >> 5, lane = t & 31;
    int g = lane >> 2, q = lane & 3;
    unsigned* Qw = sm + 128 * FST + wid * 16 * FST;

    int bx = gridDim.x - 1 - blockIdx.x;       // reversed: heavy tiles first
    int bh = blockIdx.y;
    int b  = bh >> 4;
    int h  = bh & 15;
    int m0 = bx * 128;
    int r0w = m0 + wid * 16;

    const __half* qbase = g_q + (size_t)bh * S_ * DK_;
    const __half* kbase = g_k + (size_t)bh * S_ * DK_;
    const __half* vbase = g_v + (size_t)bh * S_ * DK_;

    // ---- stage this warp's Q tile (16x64 half, already scaled) ----
    #pragma unroll
    for (int i = 0; i < 4; ++i) {
        int idx = lane + 32 * i;               // 0..127 uint4 chunks
        int row = idx >> 3, c = idx & 7;
        uint4 v = *(const uint4*)(qbase + (size_t)(r0w + row) * DK_ + c * 8);
        *(uint4*)&Qw[row * FST + c * 4] = v;
    }
    __syncwarp();

    const uint32_t Kb = smem_u32(Ksh);
    const uint32_t Vb = smem_u32(Vsh);
    const uint32_t Qb = smem_u32(Qw);

    unsigned aq[4][4];
    {
        uint32_t qaddr = Qb + (uint32_t)(lane & 15) * (FST * 4) + ((lane & 16) ? 16u : 0u);
        #pragma unroll
        for (int kk = 0; kk < 4; ++kk)
            ldsm_x4(aq[kk], qaddr + kk * 32);
    }

    const uint32_t k_lrow = (uint32_t)((lane & 7) + ((lane & 16) ? 8 : 0)) * (FST * 4)
                          + ((lane & 8) ? 16u : 0u);
    const uint32_t v_lrow = (uint32_t)((lane & 7) + ((lane & 8) ? 8 : 0)) * (FST * 4)
                          + ((lane & 16) ? 16u : 0u);

    float od[8][4];
    #pragma unroll
    for (int nt = 0; nt < 8; nt++)
        #pragma unroll
        for (int i = 0; i < 4; i++) od[nt][i] = 0.f;
    float mrow0 = -1e30f, mrow1 = -1e30f, lrow0 = 0.f, lrow1 = 0.f;

    int nkb = 2 * (bx + 1);                    // causal: key blocks 0..nkb-1

    for (int kb = 0; kb < nkb; ++kb) {
        int jb = kb * 64;
        __syncthreads();
        // ---- cooperative K/V tile fill (64x64 half each): pure uint4 copies ----
        #pragma unroll
        for (int i = 0; i < 4; ++i) {
            int idx = t + 256 * i;             // 0..1023
            int mat = idx >> 9;                // 0=K, 1=V
            int row = (idx >> 3) & 63;
            int c   = idx & 7;
            const __half* src = (mat ? vbase : kbase) + (size_t)(jb + row) * DK_ + c * 8;
            unsigned* dst = (mat ? Vsh : Ksh) + row * FST + c * 4;
            *(uint4*)dst = *(const uint4*)src;
        }
        __syncthreads();

        if (jb > r0w + 15) continue;

        int nplim = ((r0w + 15 - jb) >> 4) + 1;
        if (nplim > 4) nplim = 4;
        int ntlim = 2 * nplim;

        // ---- S = Q @ K^T ----
        float s[8][4];
        #pragma unroll
        for (int nt = 0; nt < 8; nt++)
            #pragma unroll
            for (int i = 0; i < 4; i++) s[nt][i] = 0.f;

        #pragma unroll
        for (int kk = 0; kk < 4; ++kk) {
            #pragma unroll
            for (int np = 0; np < 4; ++np) {
                if (np < nplim) {
                    unsigned bfr[4];
                    ldsm_x4(bfr, Kb + (uint32_t)np * (16 * FST * 4) + (uint32_t)kk * 32 + k_lrow);
                    mma_f16(s[2 * np    ], aq[kk], bfr[0], bfr[1]);
                    mma_f16(s[2 * np + 1], aq[kk], bfr[2], bfr[3]);
                }
            }
        }

        // ---- causal mask (diagonal region) ----
        if (jb + 63 > r0w) {
            int row0 = r0w + g, row1 = r0w + g + 8;
            #pragma unroll
            for (int nt = 0; nt < 8; ++nt) {
                if (nt < ntlim) {
                    int j0 = jb + nt * 8 + 2 * q;
                    if (j0     > row0) s[nt][0] = -1e30f;
                    if (j0 + 1 > row0) s[nt][1] = -1e30f;
                    if (j0     > row1) s[nt][2] = -1e30f;
                    if (j0 + 1 > row1) s[nt][3] = -1e30f;
                }
            }
        }

        // ---- online softmax ----
        float mx0 = -1e30f, mx1 = -1e30f;
        #pragma unroll
        for (int nt = 0; nt < 8; ++nt) {
            if (nt < ntlim) {
                mx0 = fmaxf(mx0, fmaxf(s[nt][0], s[nt][1]));
                mx1 = fmaxf(mx1, fmaxf(s[nt][2], s[nt][3]));
            }
        }
        mx0 = fmaxf(mx0, __shfl_xor_sync(0xffffffffu, mx0, 1));
        mx0 = fmaxf(mx0, __shfl_xor_sync(0xffffffffu, mx0, 2));
        mx1 = fmaxf(mx1, __shfl_xor_sync(0xffffffffu, mx1, 1));
        mx1 = fmaxf(mx1, __shfl_xor_sync(0xffffffffu, mx1, 2));

        float mn0 = fmaxf(mrow0, mx0);
        float mn1 = fmaxf(mrow1, mx1);
        float alpha0 = fexp(mrow0 - mn0);
        float alpha1 = fexp(mrow1 - mn1);
        mrow0 = mn0; mrow1 = mn1;

        unsigned ph0[8], ph1[8];
        float rs0 = 0.f, rs1 = 0.f;
        #pragma unroll
        for (int nt = 0; nt < 8; ++nt) {
            if (nt < ntlim) {
                float p0 = fexp(s[nt][0] - mn0);
                float p1 = fexp(s[nt][1] - mn0);
                float p2 = fexp(s[nt][2] - mn1);
                float p3 = fexp(s[nt][3] - mn1);
                rs0 += p0 + p1;
                rs1 += p2 + p3;
                ph0[nt] = f2h2(p0, p1);
                ph1[nt] = f2h2(p2, p3);
            }
        }
        rs0 += __shfl_xor_sync(0xffffffffu, rs0, 1);
        rs0 += __shfl_xor_sync(0xffffffffu, rs0, 2);
        rs1 += __shfl_xor_sync(0xffffffffu, rs1, 1);
        rs1 += __shfl_xor_sync(0xffffffffu, rs1, 2);
        lrow0 = lrow0 * alpha0 + rs0;
        lrow1 = lrow1 * alpha1 + rs1;

        #pragma unroll
        for (int nt = 0; nt < 8; ++nt) {
            od[nt][0] *= alpha0; od[nt][1] *= alpha0;
            od[nt][2] *= alpha1; od[nt][3] *= alpha1;
        }

        // ---- O += P @ V ----
        #pragma unroll
        for (int kk = 0; kk < 4; ++kk) {
            if (kk < nplim) {
                unsigned ap[4];
                ap[0] = ph0[2 * kk];
                ap[1] = ph1[2 * kk];
                ap[2] = ph0[2 * kk + 1];
                ap[3] = ph1[2 * kk + 1];
                #pragma unroll
                for (int np = 0; np < 4; ++np) {
                    unsigned bfr[4];
                    ldsm_x4_t(bfr, Vb + (uint32_t)kk * (16 * FST * 4) + (uint32_t)np * 32 + v_lrow);
                    mma_f16(od[2 * np    ], ap, bfr[0], bfr[1]);
                    mma_f16(od[2 * np + 1], ap, bfr[2], bfr[3]);
                }
            }
        }
    }

    // ---- epilogue: normalize + write half [B,S,D] ----
    float inv0 = 1.f / lrow0;
    float inv1 = 1.f / lrow1;
    int row0 = m0 + wid * 16 + g;
    int row1 = row0 + 8;
    __half* o0 = outh + ((size_t)b * S_ + row0) * D_ + h * DK_;
    __half* o1 = outh + ((size_t)b * S_ + row1) * D_ + h * DK_;
    #pragma unroll
    for (int nt = 0; nt < 8; ++nt) {
        int col = nt * 8 + 2 * q;
        *(unsigned*)(o0 + col) = f2h2(od[nt][0] * inv0, od[nt][1] * inv0);
        *(unsigned*)(o1 + col) = f2h2(od[nt][2] * inv1, od[nt][3] * inv1);
    }
}

// ---------------------------------------------------------------------------
// Launch: fused convert -> fused QKV projection -> flash -> output GEMM
// ---------------------------------------------------------------------------
extern "C" void kernel_launch(void* const* d_in, const int* in_sizes, int n_in,
                              void* d_out, int out_size)
{
    const float* Q   = (const float*)d_in[0];
    const float* K   = (const float*)d_in[1];
    const float* V   = (const float*)d_in[2];
    const float* W_q = (const float*)d_in[3];
    const float* b_q = (const float*)d_in[4];
    const float* W_k = (const float*)d_in[5];
    const float* b_k = (const float*)d_in[6];
    const float* W_v = (const float*)d_in[7];
    const float* b_v = (const float*)d_in[8];
    const float* W_o = (const float*)d_in[9];
    const float* b_o = (const float*)d_in[10];
    float* out = (float*)d_out;

    __half* ga;
    cudaGetSymbolAddress((void**)&ga, g_attn);

    cudaFuncSetAttribute(qkv_gemm, cudaFuncAttributeMaxDynamicSharedMemorySize, G_SMEM);
    cudaFuncSetAttribute(out_gemm, cudaFuncAttributeMaxDynamicSharedMemorySize, G_SMEM);

    cvt_all<<<dim3(512, 1, 7), 256>>>(Q, K, V, W_q, W_k, W_v, W_o);

    qkv_gemm<<<dim3(8, 32, 3), 256, G_SMEM>>>(b_q, b_k, b_v);

    flash_f16<<<dim3(S_ / 128, B_ * H_), 256>>>(ga);

    out_gemm<<<dim3(8, 32), 256, G_SMEM>>>(b_o, out);
}

// round 16
// speedup vs baseline: 1.7478x; 1.0163x over previous
#include <cuda_runtime.h>
#include <cuda_fp16.h>
#include <cstdint>

// Problem constants
#define B_  2
#define S_  2048
#define D_  1024
#define H_  16
#define DK_ 64
#define M_  (B_*S_)   // 4096 rows

// fp16 scratch (device globals: allocation-free)
__device__ __half g_qh[4194304];   // inputs converted to half
__device__ __half g_kh[4194304];
__device__ __half g_vh[4194304];
__device__ __half g_wq[1048576];   // weights converted to half
__device__ __half g_wk[1048576];
__device__ __half g_wv[1048576];
__device__ __half g_wo[1048576];
__device__ __half g_q[4194304];    // projected, [B,H,S,DK], q pre-scaled by 1/8
__device__ __half g_k[4194304];
__device__ __half g_v[4194304];
__device__ __half g_attn[4194304]; // [B,S,D] half

// ---------------------------------------------------------------------------
// helpers
// ---------------------------------------------------------------------------
__device__ __forceinline__ unsigned f2h2(float lo, float hi) {
    __half2 h = __floats2half2_rn(lo, hi);
    return *(unsigned*)&h;
}

__device__ __forceinline__ uint32_t smem_u32(const void* p) {
    uint32_t a;
    asm("{ .reg .u64 t; cvta.to.shared.u64 t, %1; cvt.u32.u64 %0, t; }" : "=r"(a) : "l"(p));
    return a;
}

__device__ __forceinline__ void mma_f16(float c[4], const unsigned a[4], unsigned b0, unsigned b1) {
    asm volatile(
        "mma.sync.aligned.m16n8k16.row.col.f32.f16.f16.f32 "
        "{%0,%1,%2,%3}, {%4,%5,%6,%7}, {%8,%9}, {%0,%1,%2,%3};"
        : "+f"(c[0]), "+f"(c[1]), "+f"(c[2]), "+f"(c[3])
        : "r"(a[0]), "r"(a[1]), "r"(a[2]), "r"(a[3]),
          "r"(b0), "r"(b1));
}

__device__ __forceinline__ void ldsm_x4(unsigned r[4], uint32_t addr) {
    asm volatile("ldmatrix.sync.aligned.m8n8.x4.shared.b16 {%0,%1,%2,%3}, [%4];"
                 : "=r"(r[0]), "=r"(r[1]), "=r"(r[2]), "=r"(r[3]) : "r"(addr));
}
__device__ __forceinline__ void ldsm_x4_t(unsigned r[4], uint32_t addr) {
    asm volatile("ldmatrix.sync.aligned.m8n8.x4.trans.shared.b16 {%0,%1,%2,%3}, [%4];"
                 : "=r"(r[0]), "=r"(r[1]), "=r"(r[2]), "=r"(r[3]) : "r"(addr));
}

#define CP16(dst, src) \
    asm volatile("cp.async.cg.shared.global [%0], [%1], 16;" :: "r"(dst), "l"(src))
#define CP_COMMIT() asm volatile("cp.async.commit_group;" ::: "memory")
#define CP_WAIT(n)  asm volatile("cp.async.wait_group %0;" :: "n"(n) : "memory")

// Fast e^x on the FMA/ALU pipes (no MUFU). Handles very negative x (mask) -> ~0.
__device__ __forceinline__ float fexp(float x) {
    float y = x * 1.44269504089f;          // log2(e)
    y = fmaxf(y, -126.0f);
    float z = __fadd_rn(y, 12582912.0f);   // rint via magic number
    int   iz = __float_as_int(z);
    float k = __fadd_rn(z, -12582912.0f);
    float f = y - k;                       // f in [-0.5, 0.5]
    float u = f * 0.69314718056f;
    float p = fmaf(u, fmaf(u, fmaf(u, fmaf(u, 0.041666668f, 0.16666667f), 0.5f), 1.0f), 1.0f);
    return __int_as_float(__float_as_int(p) + (iz << 23));  // p * 2^k
}

// ---------------------------------------------------------------------------
// Fused fp32 -> fp16 convert for all 7 tensors. blockIdx.z selects tensor.
// grid.x=512 -> 131072 threads per tensor; 4-batched loads (MLP=8).
// ---------------------------------------------------------------------------
__global__ __launch_bounds__(256)
void cvt_all(const float* __restrict__ Q, const float* __restrict__ K,
             const float* __restrict__ V, const float* __restrict__ Wq,
             const float* __restrict__ Wk, const float* __restrict__ Wv,
             const float* __restrict__ Wo)
{
    int z = blockIdx.z;
    const float* s;
    __half* d;
    int n8;
    switch (z) {
        case 0: s = Q;  d = g_qh; n8 = 524288; break;
        case 1: s = K;  d = g_kh; n8 = 524288; break;
        case 2: s = V;  d = g_vh; n8 = 524288; break;
        case 3: s = Wq; d = g_wq; n8 = 131072; break;
        case 4: s = Wk; d = g_wk; n8 = 131072; break;
        case 5: s = Wv; d = g_wv; n8 = 131072; break;
        default: s = Wo; d = g_wo; n8 = 131072; break;
    }
    int tid = blockIdx.x * 256 + threadIdx.x;     // 0..131071
    float4 a[4], b[4];
    #pragma unroll
    for (int j = 0; j < 4; ++j) {
        int i = tid + j * 131072;
        if (i < n8) {
            a[j] = ((const float4*)s)[2 * i];
            b[j] = ((const float4*)s)[2 * i + 1];
        }
    }
    #pragma unroll
    for (int j = 0; j < 4; ++j) {
        int i = tid + j * 131072;
        if (i < n8) {
            uint4 u;
            u.x = f2h2(a[j].x, a[j].y); u.y = f2h2(a[j].z, a[j].w);
            u.z = f2h2(b[j].x, b[j].y); u.w = f2h2(b[j].z, b[j].w);
            ((uint4*)d)[i] = u;
        }
    }
}

// ---------------------------------------------------------------------------
// fp16 GEMM, BK=64, cp.async 3-stage ring, 128 threads / 4 warps (2x2),
// warp tile 64x64 (halves per-SM LDSM traffic vs 32x64 at 8 warps).
// C[4096,1024] = A[4096,1024]h @ W[1024,1024]h  (+bias, *scale)
// A stage: 128 rows x 144B (128B data + 16 pad)  -> coalesced fill, CF ldmatrix.
// B stage: 64 k-rows x 272B (256B data + 16 pad) -> coalesced fill, CF ldsm_t.
// MODE 0: fp32 row-major write. MODE 1: half [B,H,S,DK] head-layout write.
// ---------------------------------------------------------------------------
#define GS_B   18432                 // A stage bytes (128*144)
#define G_STG  35840                 // + B stage (64*272)
#define G_SMEM (3 * G_STG)           // 107520

template<int MODE>
__device__ __forceinline__ void gemm_body(const __half* __restrict__ A,
                                          const __half* __restrict__ W,
                                          const float* __restrict__ bias,
                                          void* __restrict__ Cv, float scale)
{
    extern __shared__ char smc[];
    const uint32_t sb = smem_u32(smc);

    const int t    = threadIdx.x;
    const int lane = t & 31;
    const int warp = t >> 5;           // 0..3
    const int g    = lane >> 2;
    const int q    = lane & 3;

    const int bm = blockIdx.y * 128;
    const int bn = blockIdx.x * 128;
    const int wm = (warp & 1) * 64;    // 2x2 warp grid
    const int wn = (warp >> 1) * 64;

    float acc[4][8][4];
    #pragma unroll
    for (int mt = 0; mt < 4; mt++)
        #pragma unroll
        for (int nt = 0; nt < 8; nt++)
            #pragma unroll
            for (int i = 0; i < 4; i++) acc[mt][nt][i] = 0.f;

    const uint32_t a_lrow = (uint32_t)(lane & 15);
    const uint32_t a_lcol = (lane & 16) ? 16u : 0u;
    const uint32_t b_lrow = (uint32_t)((lane & 7) + ((lane & 8) ? 8 : 0));
    const uint32_t b_lcol = (lane & 16) ? 16u : 0u;

    // fill one k64 chunk (ck) into stage ck%3 via cp.async (all coalesced)
    auto fill = [&](int ck) {
        uint32_t base = sb + (uint32_t)(ck % 3) * G_STG;
        #pragma unroll
        for (int i = 0; i < 8; ++i) {              // A: 1024 chunks, 8/row
            int idx = t + 128 * i;
            int row = idx >> 3, c = idx & 7;
            CP16(base + (uint32_t)(row * 144 + c * 16),
                 A + (size_t)(bm + row) * 1024 + ck * 64 + c * 8);
        }
        #pragma unroll
        for (int i = 0; i < 8; ++i) {              // B: 1024 chunks, 16/row
            int idx = t + 128 * i;
            int row = idx >> 4, c = idx & 15;
            CP16(base + GS_B + (uint32_t)(row * 272 + c * 16),
                 W + (size_t)(ck * 64 + row) * 1024 + bn + c * 8);
        }
    };

    fill(0); CP_COMMIT();
    fill(1); CP_COMMIT();

    for (int it = 0; it < 16; ++it) {
        if (it < 15) { CP_WAIT(1); } else { CP_WAIT(0); }
        __syncthreads();                            // all warps done with stage (it-1)%3
        if (it + 2 < 16) { fill(it + 2); CP_COMMIT(); }

        uint32_t Abase = sb + (uint32_t)(it % 3) * G_STG;
        uint32_t Bbase = Abase + GS_B;
        #pragma unroll
        for (int s = 0; s < 4; ++s) {               // 4 x k16 steps
            unsigned afr[4][4];
            #pragma unroll
            for (int mt = 0; mt < 4; ++mt)
                ldsm_x4(afr[mt], Abase + (uint32_t)(wm + mt * 16 + a_lrow) * 144
                                       + (uint32_t)s * 32 + a_lcol);
            unsigned bfr[4][4];
            #pragma unroll
            for (int np = 0; np < 4; ++np)
                ldsm_x4_t(bfr[np], Bbase + ((uint32_t)s * 16 + b_lrow) * 272
                                         + (uint32_t)(wn + np * 16) * 2 + b_lcol);
            #pragma unroll
            for (int mt = 0; mt < 4; ++mt)
                #pragma unroll
                for (int np = 0; np < 4; ++np) {
                    mma_f16(acc[mt][2 * np    ], afr[mt], bfr[np][0], bfr[np][1]);
                    mma_f16(acc[mt][2 * np + 1], afr[mt], bfr[np][2], bfr[np][3]);
                }
        }
    }

    // Epilogue
    #pragma unroll
    for (int mt = 0; mt < 4; mt++) {
        int r0 = bm + wm + mt * 16 + g;
        #pragma unroll
        for (int nt = 0; nt < 8; nt++) {
            int col = bn + wn + nt * 8 + q * 2;
            float bv0 = bias[col], bv1 = bias[col + 1];
            float v00 = (acc[mt][nt][0] + bv0) * scale;
            float v01 = (acc[mt][nt][1] + bv1) * scale;
            float v10 = (acc[mt][nt][2] + bv0) * scale;
            float v11 = (acc[mt][nt][3] + bv1) * scale;
            if (MODE == 0) {
                float* C = (float*)Cv;
                float* p0 = C + (size_t)r0 * 1024 + col;
                float* p1 = C + (size_t)(r0 + 8) * 1024 + col;
                p0[0] = v00; p0[1] = v01;
                p1[0] = v10; p1[1] = v11;
            } else {
                __half* C = (__half*)Cv;
                int h  = col >> 6;
                int dk = col & 63;
                int b0r = r0 >> 11, s0r = r0 & 2047;
                int b1r = (r0 + 8) >> 11, s1r = (r0 + 8) & 2047;
                *(unsigned*)(C + (((size_t)(b0r * H_ + h) * S_ + s0r) * DK_ + dk)) = f2h2(v00, v01);
                *(unsigned*)(C + (((size_t)(b1r * H_ + h) * S_ + s1r) * DK_ + dk)) = f2h2(v10, v11);
            }
        }
    }
}

// Fused Q/K/V projection: blockIdx.z selects projection; q pre-scaled by 1/8.
__global__ __launch_bounds__(128, 2)
void qkv_gemm(const float* __restrict__ bq, const float* __restrict__ bk,
              const float* __restrict__ bv)
{
    int z = blockIdx.z;
    const __half* A = (z == 0) ? g_qh : (z == 1) ? g_kh : g_vh;
    const __half* W = (z == 0) ? g_wq : (z == 1) ? g_wk : g_wv;
    const float*  b = (z == 0) ? bq : (z == 1) ? bk : bv;
    __half*       C = (z == 0) ? g_q : (z == 1) ? g_k : g_v;
    float scale = (z == 0) ? 0.125f : 1.0f;
    gemm_body<1>(A, W, b, C, scale);
}

__global__ __launch_bounds__(128, 2)
void out_gemm(const float* __restrict__ b, float* __restrict__ C)
{
    gemm_body<0>(g_attn, g_wo, b, C, 1.0f);
}

// ---------------------------------------------------------------------------
// fp16 causal flash attention (unchanged from R15 winner).
// Reversed blockIdx.x: heavy (large-kv) tiles launch first (LPT).
// 256 threads / 8 warps, Q tile 128 (m16/warp), K/V tile 64 keys.
// smem stride 36 u32 (144B rows) -> conflict-free ldmatrix phases.
// ---------------------------------------------------------------------------
#define FST 36
#define FLASH_U32 (64*FST + 64*FST + 8*16*FST)

__global__ __launch_bounds__(256, 2)
void flash_f16(__half* __restrict__ outh)
{
    __shared__ unsigned sm[FLASH_U32];
    unsigned* Ksh = sm;
    unsigned* Vsh = sm + 64 * FST;
    int t = threadIdx.x;
    int wid = t >> 5, lane = t & 31;
    int g = lane >> 2, q = lane & 3;
    unsigned* Qw = sm + 128 * FST + wid * 16 * FST;

    int bx = gridDim.x - 1 - blockIdx.x;       // reversed: heavy tiles first
    int bh = blockIdx.y;
    int b  = bh >> 4;
    int h  = bh & 15;
    int m0 = bx * 128;
    int r0w = m0 + wid * 16;

    const __half* qbase = g_q + (size_t)bh * S_ * DK_;
    const __half* kbase = g_k + (size_t)bh * S_ * DK_;
    const __half* vbase = g_v + (size_t)bh * S_ * DK_;

    // ---- stage this warp's Q tile (16x64 half, already scaled) ----
    #pragma unroll
    for (int i = 0; i < 4; ++i) {
        int idx = lane + 32 * i;               // 0..127 uint4 chunks
        int row = idx >> 3, c = idx & 7;
        uint4 v = *(const uint4*)(qbase + (size_t)(r0w + row) * DK_ + c * 8);
        *(uint4*)&Qw[row * FST + c * 4] = v;
    }
    __syncwarp();

    const uint32_t Kb = smem_u32(Ksh);
    const uint32_t Vb = smem_u32(Vsh);
    const uint32_t Qb = smem_u32(Qw);

    unsigned aq[4][4];
    {
        uint32_t qaddr = Qb + (uint32_t)(lane & 15) * (FST * 4) + ((lane & 16) ? 16u : 0u);
        #pragma unroll
        for (int kk = 0; kk < 4; ++kk)
            ldsm_x4(aq[kk], qaddr + kk * 32);
    }

    const uint32_t k_lrow = (uint32_t)((lane & 7) + ((lane & 16) ? 8 : 0)) * (FST * 4)
                          + ((lane & 8) ? 16u : 0u);
    const uint32_t v_lrow = (uint32_t)((lane & 7) + ((lane & 8) ? 8 : 0)) * (FST * 4)
                          + ((lane & 16) ? 16u : 0u);

    float od[8][4];
    #pragma unroll
    for (int nt = 0; nt < 8; nt++)
        #pragma unroll
        for (int i = 0; i < 4; i++) od[nt][i] = 0.f;
    float mrow0 = -1e30f, mrow1 = -1e30f, lrow0 = 0.f, lrow1 = 0.f;

    int nkb = 2 * (bx + 1);                    // causal: key blocks 0..nkb-1

    for (int kb = 0; kb < nkb; ++kb) {
        int jb = kb * 64;
        __syncthreads();
        // ---- cooperative K/V tile fill (64x64 half each): pure uint4 copies ----
        #pragma unroll
        for (int i = 0; i < 4; ++i) {
            int idx = t + 256 * i;             // 0..1023
            int mat = idx >> 9;                // 0=K, 1=V
            int row = (idx >> 3) & 63;
            int c   = idx & 7;
            const __half* src = (mat ? vbase : kbase) + (size_t)(jb + row) * DK_ + c * 8;
            unsigned* dst = (mat ? Vsh : Ksh) + row * FST + c * 4;
            *(uint4*)dst = *(const uint4*)src;
        }
        __syncthreads();

        if (jb > r0w + 15) continue;

        int nplim = ((r0w + 15 - jb) >> 4) + 1;
        if (nplim > 4) nplim = 4;
        int ntlim = 2 * nplim;

        // ---- S = Q @ K^T ----
        float s[8][4];
        #pragma unroll
        for (int nt = 0; nt < 8; nt++)
            #pragma unroll
            for (int i = 0; i < 4; i++) s[nt][i] = 0.f;

        #pragma unroll
        for (int kk = 0; kk < 4; ++kk) {
            #pragma unroll
            for (int np = 0; np < 4; ++np) {
                if (np < nplim) {
                    unsigned bfr[4];
                    ldsm_x4(bfr, Kb + (uint32_t)np * (16 * FST * 4) + (uint32_t)kk * 32 + k_lrow);
                    mma_f16(s[2 * np    ], aq[kk], bfr[0], bfr[1]);
                    mma_f16(s[2 * np + 1], aq[kk], bfr[2], bfr[3]);
                }
            }
        }

        // ---- causal mask (diagonal region) ----
        if (jb + 63 > r0w) {
            int row0 = r0w + g, row1 = r0w + g + 8;
            #pragma unroll
            for (int nt = 0; nt < 8; ++nt) {
                if (nt < ntlim) {
                    int j0 = jb + nt * 8 + 2 * q;
                    if (j0     > row0) s[nt][0] = -1e30f;
                    if (j0 + 1 > row0) s[nt][1] = -1e30f;
                    if (j0     > row1) s[nt][2] = -1e30f;
                    if (j0 + 1 > row1) s[nt][3] = -1e30f;
                }
            }
        }

        // ---- online softmax ----
        float mx0 = -1e30f, mx1 = -1e30f;
        #pragma unroll
        for (int nt = 0; nt < 8; ++nt) {
            if (nt < ntlim) {
                mx0 = fmaxf(mx0, fmaxf(s[nt][0], s[nt][1]));
                mx1 = fmaxf(mx1, fmaxf(s[nt][2], s[nt][3]));
            }
        }
        mx0 = fmaxf(mx0, __shfl_xor_sync(0xffffffffu, mx0, 1));
        mx0 = fmaxf(mx0, __shfl_xor_sync(0xffffffffu, mx0, 2));
        mx1 = fmaxf(mx1, __shfl_xor_sync(0xffffffffu, mx1, 1));
        mx1 = fmaxf(mx1, __shfl_xor_sync(0xffffffffu, mx1, 2));

        float mn0 = fmaxf(mrow0, mx0);
        float mn1 = fmaxf(mrow1, mx1);
        float alpha0 = fexp(mrow0 - mn0);
        float alpha1 = fexp(mrow1 - mn1);
        mrow0 = mn0; mrow1 = mn1;

        unsigned ph0[8], ph1[8];
        float rs0 = 0.f, rs1 = 0.f;
        #pragma unroll
        for (int nt = 0; nt < 8; ++nt) {
            if (nt < ntlim) {
                float p0 = fexp(s[nt][0] - mn0);
                float p1 = fexp(s[nt][1] - mn0);
                float p2 = fexp(s[nt][2] - mn1);
                float p3 = fexp(s[nt][3] - mn1);
                rs0 += p0 + p1;
                rs1 += p2 + p3;
                ph0[nt] = f2h2(p0, p1);
                ph1[nt] = f2h2(p2, p3);
            }
        }
        rs0 += __shfl_xor_sync(0xffffffffu, rs0, 1);
        rs0 += __shfl_xor_sync(0xffffffffu, rs0, 2);
        rs1 += __shfl_xor_sync(0xffffffffu, rs1, 1);
        rs1 += __shfl_xor_sync(0xffffffffu, rs1, 2);
        lrow0 = lrow0 * alpha0 + rs0;
        lrow1 = lrow1 * alpha1 + rs1;

        #pragma unroll
        for (int nt = 0; nt < 8; ++nt) {
            od[nt][0] *= alpha0; od[nt][1] *= alpha0;
            od[nt][2] *= alpha1; od[nt][3] *= alpha1;
        }

        // ---- O += P @ V ----
        #pragma unroll
        for (int kk = 0; kk < 4; ++kk) {
            if (kk < nplim) {
                unsigned ap[4];
                ap[0] = ph0[2 * kk];
                ap[1] = ph1[2 * kk];
                ap[2] = ph0[2 * kk + 1];
                ap[3] = ph1[2 * kk + 1];
                #pragma unroll
                for (int np = 0; np < 4; ++np) {
                    unsigned bfr[4];
                    ldsm_x4_t(bfr, Vb + (uint32_t)kk * (16 * FST * 4) + (uint32_t)np * 32 + v_lrow);
                    mma_f16(od[2 * np    ], ap, bfr[0], bfr[1]);
                    mma_f16(od[2 * np + 1], ap, bfr[2], bfr[3]);
                }
            }
        }
    }

    // ---- epilogue: normalize + write half [B,S,D] ----
    float inv0 = 1.f / lrow0;
    float inv1 = 1.f / lrow1;
    int row0 = m0 + wid * 16 + g;
    int row1 = row0 + 8;
    __half* o0 = outh + ((size_t)b * S_ + row0) * D_ + h * DK_;
    __half* o1 = outh + ((size_t)b * S_ + row1) * D_ + h * DK_;
    #pragma unroll
    for (int nt = 0; nt < 8; ++nt) {
        int col = nt * 8 + 2 * q;
        *(unsigned*)(o0 + col) = f2h2(od[nt][0] * inv0, od[nt][1] * inv0);
        *(unsigned*)(o1 + col) = f2h2(od[nt][2] * inv1, od[nt][3] * inv1);
    }
}

// ---------------------------------------------------------------------------
// Launch: fused convert -> fused QKV projection -> flash -> output GEMM
// ---------------------------------------------------------------------------
extern "C" void kernel_launch(void* const* d_in, const int* in_sizes, int n_in,
                              void* d_out, int out_size)
{
    const float* Q   = (const float*)d_in[0];
    const float* K   = (const float*)d_in[1];
    const float* V   = (const float*)d_in[2];
    const float* W_q = (const float*)d_in[3];
    const float* b_q = (const float*)d_in[4];
    const float* W_k = (const float*)d_in[5];
    const float* b_k = (const float*)d_in[6];
    const float* W_v = (const float*)d_in[7];
    const float* b_v = (const float*)d_in[8];
    const float* W_o = (const float*)d_in[9];
    const float* b_o = (const float*)d_in[10];
    float* out = (float*)d_out;

    __half* ga;
    cudaGetSymbolAddress((void**)&ga, g_attn);

    cudaFuncSetAttribute(qkv_gemm, cudaFuncAttributeMaxDynamicSharedMemorySize, G_SMEM);
    cudaFuncSetAttribute(out_gemm, cudaFuncAttributeMaxDynamicSharedMemorySize, G_SMEM);

    cvt_all<<<dim3(512, 1, 7), 256>>>(Q, K, V, W_q, W_k, W_v, W_o);

    qkv_gemm<<<dim3(8, 32, 3), 128, G_SMEM>>>(b_q, b_k, b_v);

    flash_f16<<<dim3(S_ / 128, B_ * H_), 256>>>(ga);

    out_gemm<<<dim3(8, 32), 128, G_SMEM>>>(b_o, out);
}

// round 17
// speedup vs baseline: 1.7978x; 1.0286x over previous
#include <cuda_runtime.h>
#include <cuda_fp16.h>
#include <cstdint>

// Problem constants
#define B_  2
#define S_  2048
#define D_  1024
#define H_  16
#define DK_ 64
#define M_  (B_*S_)   // 4096 rows

// fp16 scratch (device globals: allocation-free)
__device__ __half g_qh[4194304];   // inputs converted to half
__device__ __half g_kh[4194304];
__device__ __half g_vh[4194304];
__device__ __half g_wq[1048576];   // weights converted to half
__device__ __half g_wk[1048576];
__device__ __half g_wv[1048576];
__device__ __half g_wo[1048576];
__device__ __half g_q[4194304];    // projected, [B,H,S,DK], q pre-scaled by 1/8
__device__ __half g_k[4194304];
__device__ __half g_v[4194304];
__device__ __half g_attn[4194304]; // [B,S,D] half

// ---------------------------------------------------------------------------
// helpers
// ---------------------------------------------------------------------------
__device__ __forceinline__ unsigned f2h2(float lo, float hi) {
    __half2 h = __floats2half2_rn(lo, hi);
    return *(unsigned*)&h;
}

__device__ __forceinline__ uint32_t smem_u32(const void* p) {
    uint32_t a;
    asm("{ .reg .u64 t; cvta.to.shared.u64 t, %1; cvt.u32.u64 %0, t; }" : "=r"(a) : "l"(p));
    return a;
}

__device__ __forceinline__ void mma_f16(float c[4], const unsigned a[4], unsigned b0, unsigned b1) {
    asm volatile(
        "mma.sync.aligned.m16n8k16.row.col.f32.f16.f16.f32 "
        "{%0,%1,%2,%3}, {%4,%5,%6,%7}, {%8,%9}, {%0,%1,%2,%3};"
        : "+f"(c[0]), "+f"(c[1]), "+f"(c[2]), "+f"(c[3])
        : "r"(a[0]), "r"(a[1]), "r"(a[2]), "r"(a[3]),
          "r"(b0), "r"(b1));
}

__device__ __forceinline__ void ldsm_x4(unsigned r[4], uint32_t addr) {
    asm volatile("ldmatrix.sync.aligned.m8n8.x4.shared.b16 {%0,%1,%2,%3}, [%4];"
                 : "=r"(r[0]), "=r"(r[1]), "=r"(r[2]), "=r"(r[3]) : "r"(addr));
}
__device__ __forceinline__ void ldsm_x4_t(unsigned r[4], uint32_t addr) {
    asm volatile("ldmatrix.sync.aligned.m8n8.x4.trans.shared.b16 {%0,%1,%2,%3}, [%4];"
                 : "=r"(r[0]), "=r"(r[1]), "=r"(r[2]), "=r"(r[3]) : "r"(addr));
}

#define CP16(dst, src) \
    asm volatile("cp.async.cg.shared.global [%0], [%1], 16;" :: "r"(dst), "l"(src))
#define CP_COMMIT() asm volatile("cp.async.commit_group;" ::: "memory")
#define CP_WAIT(n)  asm volatile("cp.async.wait_group %0;" :: "n"(n) : "memory")

// Fast e^x on the FMA/ALU pipes (no MUFU). Handles very negative x (mask) -> ~0.
__device__ __forceinline__ float fexp(float x) {
    float y = x * 1.44269504089f;          // log2(e)
    y = fmaxf(y, -126.0f);
    float z = __fadd_rn(y, 12582912.0f);   // rint via magic number
    int   iz = __float_as_int(z);
    float k = __fadd_rn(z, -12582912.0f);
    float f = y - k;                       // f in [-0.5, 0.5]
    float u = f * 0.69314718056f;
    float p = fmaf(u, fmaf(u, fmaf(u, fmaf(u, 0.041666668f, 0.16666667f), 0.5f), 1.0f), 1.0f);
    return __int_as_float(__float_as_int(p) + (iz << 23));  // p * 2^k
}

// ---------------------------------------------------------------------------
// Fused fp32 -> fp16 convert for all 7 tensors. blockIdx.z selects tensor.
// grid.x=512 -> 131072 threads per tensor; 4-batched loads (MLP=8).
// ---------------------------------------------------------------------------
__global__ __launch_bounds__(256)
void cvt_all(const float* __restrict__ Q, const float* __restrict__ K,
             const float* __restrict__ V, const float* __restrict__ Wq,
             const float* __restrict__ Wk, const float* __restrict__ Wv,
             const float* __restrict__ Wo)
{
    int z = blockIdx.z;
    const float* s;
    __half* d;
    int n8;
    switch (z) {
        case 0: s = Q;  d = g_qh; n8 = 524288; break;
        case 1: s = K;  d = g_kh; n8 = 524288; break;
        case 2: s = V;  d = g_vh; n8 = 524288; break;
        case 3: s = Wq; d = g_wq; n8 = 131072; break;
        case 4: s = Wk; d = g_wk; n8 = 131072; break;
        case 5: s = Wv; d = g_wv; n8 = 131072; break;
        default: s = Wo; d = g_wo; n8 = 131072; break;
    }
    int tid = blockIdx.x * 256 + threadIdx.x;     // 0..131071
    float4 a[4], b[4];
    #pragma unroll
    for (int j = 0; j < 4; ++j) {
        int i = tid + j * 131072;
        if (i < n8) {
            a[j] = ((const float4*)s)[2 * i];
            b[j] = ((const float4*)s)[2 * i + 1];
        }
    }
    #pragma unroll
    for (int j = 0; j < 4; ++j) {
        int i = tid + j * 131072;
        if (i < n8) {
            uint4 u;
            u.x = f2h2(a[j].x, a[j].y); u.y = f2h2(a[j].z, a[j].w);
            u.z = f2h2(b[j].x, b[j].y); u.w = f2h2(b[j].z, b[j].w);
            ((uint4*)d)[i] = u;
        }
    }
}

// ---------------------------------------------------------------------------
// fp16 GEMM, BK=64, cp.async 3-stage ring, 128 threads / 4 warps (2x2),
// warp tile 64x64. (Unchanged from R16.)
// C[4096,1024] = A[4096,1024]h @ W[1024,1024]h  (+bias, *scale)
// A stage: 128 rows x 144B; B stage: 64 k-rows x 272B (both CF ldmatrix).
// MODE 0: fp32 row-major write. MODE 1: half [B,H,S,DK] head-layout write.
// ---------------------------------------------------------------------------
#define GS_B   18432                 // A stage bytes (128*144)
#define G_STG  35840                 // + B stage (64*272)
#define G_SMEM (3 * G_STG)           // 107520

template<int MODE>
__device__ __forceinline__ void gemm_body(const __half* __restrict__ A,
                                          const __half* __restrict__ W,
                                          const float* __restrict__ bias,
                                          void* __restrict__ Cv, float scale)
{
    extern __shared__ char smc[];
    const uint32_t sb = smem_u32(smc);

    const int t    = threadIdx.x;
    const int lane = t & 31;
    const int warp = t >> 5;           // 0..3
    const int g    = lane >> 2;
    const int q    = lane & 3;

    const int bm = blockIdx.y * 128;
    const int bn = blockIdx.x * 128;
    const int wm = (warp & 1) * 64;    // 2x2 warp grid
    const int wn = (warp >> 1) * 64;

    float acc[4][8][4];
    #pragma unroll
    for (int mt = 0; mt < 4; mt++)
        #pragma unroll
        for (int nt = 0; nt < 8; nt++)
            #pragma unroll
            for (int i = 0; i < 4; i++) acc[mt][nt][i] = 0.f;

    const uint32_t a_lrow = (uint32_t)(lane & 15);
    const uint32_t a_lcol = (lane & 16) ? 16u : 0u;
    const uint32_t b_lrow = (uint32_t)((lane & 7) + ((lane & 8) ? 8 : 0));
    const uint32_t b_lcol = (lane & 16) ? 16u : 0u;

    auto fill = [&](int ck) {
        uint32_t base = sb + (uint32_t)(ck % 3) * G_STG;
        #pragma unroll
        for (int i = 0; i < 8; ++i) {              // A: 1024 chunks, 8/row
            int idx = t + 128 * i;
            int row = idx >> 3, c = idx & 7;
            CP16(base + (uint32_t)(row * 144 + c * 16),
                 A + (size_t)(bm + row) * 1024 + ck * 64 + c * 8);
        }
        #pragma unroll
        for (int i = 0; i < 8; ++i) {              // B: 1024 chunks, 16/row
            int idx = t + 128 * i;
            int row = idx >> 4, c = idx & 15;
            CP16(base + GS_B + (uint32_t)(row * 272 + c * 16),
                 W + (size_t)(ck * 64 + row) * 1024 + bn + c * 8);
        }
    };

    fill(0); CP_COMMIT();
    fill(1); CP_COMMIT();

    for (int it = 0; it < 16; ++it) {
        if (it < 15) { CP_WAIT(1); } else { CP_WAIT(0); }
        __syncthreads();                            // all warps done with stage (it-1)%3
        if (it + 2 < 16) { fill(it + 2); CP_COMMIT(); }

        uint32_t Abase = sb + (uint32_t)(it % 3) * G_STG;
        uint32_t Bbase = Abase + GS_B;
        #pragma unroll
        for (int s = 0; s < 4; ++s) {               // 4 x k16 steps
            unsigned afr[4][4];
            #pragma unroll
            for (int mt = 0; mt < 4; ++mt)
                ldsm_x4(afr[mt], Abase + (uint32_t)(wm + mt * 16 + a_lrow) * 144
                                       + (uint32_t)s * 32 + a_lcol);
            unsigned bfr[4][4];
            #pragma unroll
            for (int np = 0; np < 4; ++np)
                ldsm_x4_t(bfr[np], Bbase + ((uint32_t)s * 16 + b_lrow) * 272
                                         + (uint32_t)(wn + np * 16) * 2 + b_lcol);
            #pragma unroll
            for (int mt = 0; mt < 4; ++mt)
                #pragma unroll
                for (int np = 0; np < 4; ++np) {
                    mma_f16(acc[mt][2 * np    ], afr[mt], bfr[np][0], bfr[np][1]);
                    mma_f16(acc[mt][2 * np + 1], afr[mt], bfr[np][2], bfr[np][3]);
                }
        }
    }

    // Epilogue
    #pragma unroll
    for (int mt = 0; mt < 4; mt++) {
        int r0 = bm + wm + mt * 16 + g;
        #pragma unroll
        for (int nt = 0; nt < 8; nt++) {
            int col = bn + wn + nt * 8 + q * 2;
            float bv0 = bias[col], bv1 = bias[col + 1];
            float v00 = (acc[mt][nt][0] + bv0) * scale;
            float v01 = (acc[mt][nt][1] + bv1) * scale;
            float v10 = (acc[mt][nt][2] + bv0) * scale;
            float v11 = (acc[mt][nt][3] + bv1) * scale;
            if (MODE == 0) {
                float* C = (float*)Cv;
                float* p0 = C + (size_t)r0 * 1024 + col;
                float* p1 = C + (size_t)(r0 + 8) * 1024 + col;
                p0[0] = v00; p0[1] = v01;
                p1[0] = v10; p1[1] = v11;
            } else {
                __half* C = (__half*)Cv;
                int h  = col >> 6;
                int dk = col & 63;
                int b0r = r0 >> 11, s0r = r0 & 2047;
                int b1r = (r0 + 8) >> 11, s1r = (r0 + 8) & 2047;
                *(unsigned*)(C + (((size_t)(b0r * H_ + h) * S_ + s0r) * DK_ + dk)) = f2h2(v00, v01);
                *(unsigned*)(C + (((size_t)(b1r * H_ + h) * S_ + s1r) * DK_ + dk)) = f2h2(v10, v11);
            }
        }
    }
}

// Fused Q/K/V projection: blockIdx.z selects projection; q pre-scaled by 1/8.
__global__ __launch_bounds__(128, 2)
void qkv_gemm(const float* __restrict__ bq, const float* __restrict__ bk,
              const float* __restrict__ bv)
{
    int z = blockIdx.z;
    const __half* A = (z == 0) ? g_qh : (z == 1) ? g_kh : g_vh;
    const __half* W = (z == 0) ? g_wq : (z == 1) ? g_wk : g_wv;
    const float*  b = (z == 0) ? bq : (z == 1) ? bk : bv;
    __half*       C = (z == 0) ? g_q : (z == 1) ? g_k : g_v;
    float scale = (z == 0) ? 0.125f : 1.0f;
    gemm_body<1>(A, W, b, C, scale);
}

__global__ __launch_bounds__(128, 2)
void out_gemm(const float* __restrict__ b, float* __restrict__ C)
{
    gemm_body<0>(g_attn, g_wo, b, C, 1.0f);
}

// ---------------------------------------------------------------------------
// fp16 causal flash attention, cp.async 3-stage K/V ring.
// Reversed blockIdx.x (LPT). 256 threads / 8 warps, Q tile 128, K/V tile 64.
// Stage rows 144B (128B data + 16 pad) -> coalesced fills + CF ldmatrix.
// One CP_WAIT + one __syncthreads per key block; fill(kb+2) overlaps compute(kb).
// ---------------------------------------------------------------------------
#define F_MAT   9216                 // one 64x64 half tile, 144B rows
#define F_STAGE (2 * F_MAT)          // K + V = 18432
#define F_QOFF  (3 * F_STAGE)        // 55296
#define F_SMEM  (F_QOFF + 18432)     // 73728

__global__ __launch_bounds__(256, 2)
void flash_f16(__half* __restrict__ outh)
{
    extern __shared__ char smc[];
    const uint32_t sb = smem_u32(smc);
    int t = threadIdx.x;
    int wid = t >> 5, lane = t & 31;
    int g = lane >> 2, q = lane & 3;

    int bx = gridDim.x - 1 - blockIdx.x;       // reversed: heavy tiles first
    int bh = blockIdx.y;
    int b  = bh >> 4;
    int h  = bh & 15;
    int m0 = bx * 128;
    int r0w = m0 + wid * 16;

    const __half* qbase = g_q + (size_t)bh * S_ * DK_;
    const __half* kbase = g_k + (size_t)bh * S_ * DK_;
    const __half* vbase = g_v + (size_t)bh * S_ * DK_;

    int nkb = 2 * (bx + 1);                    // causal: key blocks 0..nkb-1

    // ---- K/V cp.async ring fills ----
    auto fill_kv = [&](int kb) {
        uint32_t base = sb + (uint32_t)(kb % 3) * F_STAGE;
        #pragma unroll
        for (int i = 0; i < 4; ++i) {
            int idx = t + 256 * i;             // 0..1023 chunks
            int mat = idx >> 9;                // 0=K, 1=V
            int row = (idx >> 3) & 63;
            int c   = idx & 7;
            const __half* src = (mat ? vbase : kbase) + (size_t)(kb * 64 + row) * DK_ + c * 8;
            CP16(base + (uint32_t)(mat * F_MAT + row * 144 + c * 16), src);
        }
    };

    fill_kv(0); CP_COMMIT();
    if (nkb > 1) { fill_kv(1); CP_COMMIT(); }

    // ---- stage this warp's Q tile (16x64 half, already scaled) ----
    #pragma unroll
    for (int i = 0; i < 4; ++i) {
        int idx = lane + 32 * i;               // 0..127 uint4 chunks
        int row = idx >> 3, c = idx & 7;
        uint4 v = *(const uint4*)(qbase + (size_t)(r0w + row) * DK_ + c * 8);
        *(uint4*)(smc + F_QOFF + wid * (16 * 144) + row * 144 + c * 16) = v;
    }
    __syncwarp();

    // Q A-frags via ldmatrix.x4
    unsigned aq[4][4];
    {
        uint32_t qaddr = sb + F_QOFF + (uint32_t)wid * (16 * 144)
                       + (uint32_t)(lane & 15) * 144 + ((lane & 16) ? 16u : 0u);
        #pragma unroll
        for (int kk = 0; kk < 4; ++kk)
            ldsm_x4(aq[kk], qaddr + kk * 32);
    }

    const uint32_t k_lrow = (uint32_t)((lane & 7) + ((lane & 16) ? 8 : 0)) * 144
                          + ((lane & 8) ? 16u : 0u);
    const uint32_t v_lrow = (uint32_t)((lane & 7) + ((lane & 8) ? 8 : 0)) * 144
                          + ((lane & 16) ? 16u : 0u);

    float od[8][4];
    #pragma unroll
    for (int nt = 0; nt < 8; nt++)
        #pragma unroll
        for (int i = 0; i < 4; i++) od[nt][i] = 0.f;
    float mrow0 = -1e30f, mrow1 = -1e30f, lrow0 = 0.f, lrow1 = 0.f;

    for (int kb = 0; kb < nkb; ++kb) {
        int jb = kb * 64;
        if (kb < nkb - 1) { CP_WAIT(1); } else { CP_WAIT(0); }
        __syncthreads();                       // stage kb ready for ALL threads;
                                               // consumers of stage (kb-1) done
        if (kb + 2 < nkb) { fill_kv(kb + 2); CP_COMMIT(); }

        if (jb > r0w + 15) continue;           // fully-future block for this warp

        uint32_t Kb = sb + (uint32_t)(kb % 3) * F_STAGE;
        uint32_t Vb = Kb + F_MAT;

        int nplim = ((r0w + 15 - jb) >> 4) + 1;
        if (nplim > 4) nplim = 4;
        int ntlim = 2 * nplim;

        // ---- S = Q @ K^T ----
        float s[8][4];
        #pragma unroll
        for (int nt = 0; nt < 8; nt++)
            #pragma unroll
            for (int i = 0; i < 4; i++) s[nt][i] = 0.f;

        #pragma unroll
        for (int kk = 0; kk < 4; ++kk) {
            #pragma unroll
            for (int np = 0; np < 4; ++np) {
                if (np < nplim) {
                    unsigned bfr[4];
                    ldsm_x4(bfr, Kb + (uint32_t)np * (16 * 144) + (uint32_t)kk * 32 + k_lrow);
                    mma_f16(s[2 * np    ], aq[kk], bfr[0], bfr[1]);
                    mma_f16(s[2 * np + 1], aq[kk], bfr[2], bfr[3]);
                }
            }
        }

        // ---- causal mask (diagonal region) ----
        if (jb + 63 > r0w) {
            int row0 = r0w + g, row1 = r0w + g + 8;
            #pragma unroll
            for (int nt = 0; nt < 8; ++nt) {
                if (nt < ntlim) {
                    int j0 = jb + nt * 8 + 2 * q;
                    if (j0     > row0) s[nt][0] = -1e30f;
                    if (j0 + 1 > row0) s[nt][1] = -1e30f;
                    if (j0     > row1) s[nt][2] = -1e30f;
                    if (j0 + 1 > row1) s[nt][3] = -1e30f;
                }
            }
        }

        // ---- online softmax ----
        float mx0 = -1e30f, mx1 = -1e30f;
        #pragma unroll
        for (int nt = 0; nt < 8; ++nt) {
            if (nt < ntlim) {
                mx0 = fmaxf(mx0, fmaxf(s[nt][0], s[nt][1]));
                mx1 = fmaxf(mx1, fmaxf(s[nt][2], s[nt][3]));
            }
        }
        mx0 = fmaxf(mx0, __shfl_xor_sync(0xffffffffu, mx0, 1));
        mx0 = fmaxf(mx0, __shfl_xor_sync(0xffffffffu, mx0, 2));
        mx1 = fmaxf(mx1, __shfl_xor_sync(0xffffffffu, mx1, 1));
        mx1 = fmaxf(mx1, __shfl_xor_sync(0xffffffffu, mx1, 2));

        float mn0 = fmaxf(mrow0, mx0);
        float mn1 = fmaxf(mrow1, mx1);
        float alpha0 = fexp(mrow0 - mn0);
        float alpha1 = fexp(mrow1 - mn1);
        mrow0 = mn0; mrow1 = mn1;

        unsigned ph0[8], ph1[8];
        float rs0 = 0.f, rs1 = 0.f;
        #pragma unroll
        for (int nt = 0; nt < 8; ++nt) {
            if (nt < ntlim) {
                float p0 = fexp(s[nt][0] - mn0);
                float p1 = fexp(s[nt][1] - mn0);
                float p2 = fexp(s[nt][2] - mn1);
                float p3 = fexp(s[nt][3] - mn1);
                rs0 += p0 + p1;
                rs1 += p2 + p3;
                ph0[nt] = f2h2(p0, p1);
                ph1[nt] = f2h2(p2, p3);
            }
        }
        rs0 += __shfl_xor_sync(0xffffffffu, rs0, 1);
        rs0 += __shfl_xor_sync(0xffffffffu, rs0, 2);
        rs1 += __shfl_xor_sync(0xffffffffu, rs1, 1);
        rs1 += __shfl_xor_sync(0xffffffffu, rs1, 2);
        lrow0 = lrow0 * alpha0 + rs0;
        lrow1 = lrow1 * alpha1 + rs1;

        #pragma unroll
        for (int nt = 0; nt < 8; ++nt) {
            od[nt][0] *= alpha0; od[nt][1] *= alpha0;
            od[nt][2] *= alpha1; od[nt][3] *= alpha1;
        }

        // ---- O += P @ V ----
        #pragma unroll
        for (int kk = 0; kk < 4; ++kk) {
            if (kk < nplim) {
                unsigned ap[4];
                ap[0] = ph0[2 * kk];
                ap[1] = ph1[2 * kk];
                ap[2] = ph0[2 * kk + 1];
                ap[3] = ph1[2 * kk + 1];
                #pragma unroll
                for (int np = 0; np < 4; ++np) {
                    unsigned bfr[4];
                    ldsm_x4_t(bfr, Vb + (uint32_t)kk * (16 * 144) + (uint32_t)np * 32 + v_lrow);
                    mma_f16(od[2 * np    ], ap, bfr[0], bfr[1]);
                    mma_f16(od[2 * np + 1], ap, bfr[2], bfr[3]);
                }
            }
        }
    }

    // ---- epilogue: normalize + write half [B,S,D] ----
    float inv0 = 1.f / lrow0;
    float inv1 = 1.f / lrow1;
    int row0 = m0 + wid * 16 + g;
    int row1 = row0 + 8;
    __half* o0 = outh + ((size_t)b * S_ + row0) * D_ + h * DK_;
    __half* o1 = outh + ((size_t)b * S_ + row1) * D_ + h * DK_;
    #pragma unroll
    for (int nt = 0; nt < 8; ++nt) {
        int col = nt * 8 + 2 * q;
        *(unsigned*)(o0 + col) = f2h2(od[nt][0] * inv0, od[nt][1] * inv0);
        *(unsigned*)(o1 + col) = f2h2(od[nt][2] * inv1, od[nt][3] * inv1);
    }
}

// ---------------------------------------------------------------------------
// Launch: fused convert -> fused QKV projection -> flash -> output GEMM
// ---------------------------------------------------------------------------
extern "C" void kernel_launch(void* const* d_in, const int* in_sizes, int n_in,
                              void* d_out, int out_size)
{
    const float* Q   = (const float*)d_in[0];
    const float* K   = (const float*)d_in[1];
    const float* V   = (const float*)d_in[2];
    const float* W_q = (const float*)d_in[3];
    const float* b_q = (const float*)d_in[4];
    const float* W_k = (const float*)d_in[5];
    const float* b_k = (const float*)d_in[6];
    const float* W_v = (const float*)d_in[7];
    const float* b_v = (const float*)d_in[8];
    const float* W_o = (const float*)d_in[9];
    const float* b_o = (const float*)d_in[10];
    float* out = (float*)d_out;

    __half* ga;
    cudaGetSymbolAddress((void**)&ga, g_attn);

    cudaFuncSetAttribute(qkv_gemm, cudaFuncAttributeMaxDynamicSharedMemorySize, G_SMEM);
    cudaFuncSetAttribute(out_gemm, cudaFuncAttributeMaxDynamicSharedMemorySize, G_SMEM);
    cudaFuncSetAttribute(flash_f16, cudaFuncAttributeMaxDynamicSharedMemorySize, F_SMEM);

    cvt_all<<<dim3(512, 1, 7), 256>>>(Q, K, V, W_q, W_k, W_v, W_o);

    qkv_gemm<<<dim3(8, 32, 3), 128, G_SMEM>>>(b_q, b_k, b_v);

    flash_f16<<<dim3(S_ / 128, B_ * H_), 256, F_SMEM>>>(ga);

    out_gemm<<<dim3(8, 32), 128, G_SMEM>>>(b_o, out);
}